// round 2
// baseline (speedup 1.0000x reference)
#include <cuda_runtime.h>

#define B    512
#define L    32768
#define WSZ  100                 // WINDOW*3 - 2
#define NOUT (L - WSZ + 1)       // 32669
#define TPB  128
#define KPT  32
#define CHUNK (TPB * KPT)        // 4096 outputs per block
#define STAGE (CHUNK + WSZ - 1)  // 4195 staged inputs
#define RGROUPS 8
#define ROWS_PER_G (B / RGROUPS) // 64

// Scratch (static device arrays — no allocation in kernel_launch)
__device__ float g_corr[(size_t)B * NOUT];
__device__ float g_partial[RGROUPS * NOUT];
__device__ float g_avg[NOUT];

// K1: per-row windowed correlation, exact sliding sums.
__global__ __launch_bounds__(TPB) void corr_kernel(const float* __restrict__ x) {
    __shared__ float sa[STAGE];
    __shared__ float sb[STAGE];
    const int row = blockIdx.y;
    const int c0  = blockIdx.x * CHUNK;
    const float* __restrict__ x1 = x + (size_t)row * (2 * L);
    const float* __restrict__ x2 = x1 + L;

    for (int i = threadIdx.x; i < STAGE; i += TPB) {
        int idx = c0 + i;
        float a = 0.f, b = 0.f;
        if (idx < L) { a = x1[idx]; b = x2[idx]; }
        sa[i] = a; sb[i] = b;
    }
    __syncthreads();

    const int base = threadIdx.x * KPT;
    float s1 = 0.f, s2 = 0.f, s11 = 0.f, s22 = 0.f, s12 = 0.f;
    #pragma unroll 5
    for (int i = 0; i < WSZ; i++) {
        float a = sa[base + i], b = sb[base + i];
        s1 += a; s2 += b; s11 += a * a; s22 += b * b; s12 += a * b;
    }

    const float invw = 1.0f / (float)WSZ;
    float* __restrict__ orow = g_corr + (size_t)row * NOUT;
    #pragma unroll
    for (int k = 0; k < KPT; k++) {
        int j = c0 + base + k;
        if (j < NOUT) {
            float cov = s12 - s1 * s2 * invw;
            float v1  = s11 - s1 * s1 * invw;
            float v2  = s22 - s2 * s2 * invw;
            orow[j] = cov * rsqrtf(v1 * v2);
        }
        if (k + 1 < KPT) {
            float an = sa[base + WSZ + k], bn = sb[base + WSZ + k];
            float ao = sa[base + k],       bo = sb[base + k];
            s1  += an - ao;
            s2  += bn - bo;
            s11 += an * an - ao * ao;
            s22 += bn * bn - bo * bo;
            s12 += an * bn - ao * bo;
        }
    }
}

// K2: partial column sums over 64-row groups (coalesced across columns).
__global__ __launch_bounds__(256) void colsum_kernel() {
    int c = blockIdx.x * blockDim.x + threadIdx.x;
    int g = blockIdx.y;
    if (c >= NOUT) return;
    const float* __restrict__ p = g_corr + (size_t)g * ROWS_PER_G * NOUT + c;
    float s = 0.f;
    #pragma unroll
    for (int r = 0; r < ROWS_PER_G; r++) s += p[(size_t)r * NOUT];
    g_partial[g * NOUT + c] = s;
}

// K2b: collapse partials -> avg.
__global__ __launch_bounds__(256) void avg_kernel() {
    int c = blockIdx.x * blockDim.x + threadIdx.x;
    if (c >= NOUT) return;
    float s = 0.f;
    #pragma unroll
    for (int g = 0; g < RGROUPS; g++) s += g_partial[g * NOUT + c];
    g_avg[c] = s * (1.0f / (float)B);
}

// K3: out = relu(corr - avg)
__global__ __launch_bounds__(256) void final_kernel(float* __restrict__ out) {
    int c = blockIdx.x * blockDim.x + threadIdx.x;
    int r = blockIdx.y;
    if (c >= NOUT) return;
    size_t i = (size_t)r * NOUT + c;
    float v = g_corr[i] - g_avg[c];
    out[i] = v > 0.f ? v : 0.f;
}

extern "C" void kernel_launch(void* const* d_in, const int* in_sizes, int n_in,
                              void* d_out, int out_size) {
    const float* x = (const float*)d_in[0];
    float* out = (float*)d_out;

    dim3 g1((NOUT + CHUNK - 1) / CHUNK, B);
    corr_kernel<<<g1, TPB>>>(x);

    dim3 g2((NOUT + 255) / 256, RGROUPS);
    colsum_kernel<<<g2, 256>>>();

    avg_kernel<<<(NOUT + 255) / 256, 256>>>();

    dim3 g3((NOUT + 255) / 256, B);
    final_kernel<<<g3, 256>>>(out);
}

// round 3
// speedup vs baseline: 5.7189x; 5.7189x over previous
#include <cuda_runtime.h>

#define B    512
#define L    32768
#define WSZ  100                 // WINDOW*3 - 2
#define NOUT (L - WSZ + 1)       // 32669
#define TPB  128
#define KPT  32
#define CHUNK (TPB * KPT)        // 4096 outputs per block
#define STAGE (CHUNK + WSZ - 1)  // 4195 staged inputs
#define RGROUPS 8
#define ROWS_PER_G (B / RGROUPS) // 64

// Bank-conflict-avoiding index: stride-32 float accesses map to distinct banks.
#define IX(i) ((i) + ((i) >> 5))
#define SPAD  (STAGE + (STAGE >> 5) + 4)   // padded shared size

// Scratch (static device arrays — no allocation in kernel_launch)
__device__ float g_corr[(size_t)B * NOUT];
__device__ float g_partial[RGROUPS * NOUT];
__device__ float g_avg[NOUT];

// K1: per-row windowed correlation, exact sliding sums.
// Shared accesses padded (conflict-free); output transposed through shared
// for coalesced global stores.
__global__ __launch_bounds__(TPB) void corr_kernel(const float* __restrict__ x) {
    __shared__ float sa[SPAD];
    __shared__ float sb[SPAD];
    const int row = blockIdx.y;
    const int c0  = blockIdx.x * CHUNK;
    const float* __restrict__ x1 = x + (size_t)row * (2 * L);
    const float* __restrict__ x2 = x1 + L;

    // Stage inputs (coalesced gmem reads; padded shared writes conflict-free:
    // consecutive i within a 32-group -> consecutive banks).
    for (int i = threadIdx.x; i < STAGE; i += TPB) {
        int idx = c0 + i;
        float a = 0.f, b = 0.f;
        if (idx < L) { a = x1[idx]; b = x2[idx]; }
        sa[IX(i)] = a; sb[IX(i)] = b;
    }
    __syncthreads();

    const int base = threadIdx.x * KPT;
    float s1 = 0.f, s2 = 0.f, s11 = 0.f, s22 = 0.f, s12 = 0.f;
    #pragma unroll 10
    for (int i = 0; i < WSZ; i++) {
        float a = sa[IX(base + i)], b = sb[IX(base + i)];
        s1 += a; s2 += b; s11 += a * a; s22 += b * b; s12 += a * b;
    }

    const float invw = 1.0f / (float)WSZ;
    float res[KPT];
    #pragma unroll
    for (int k = 0; k < KPT; k++) {
        float cov = s12 - s1 * s2 * invw;
        float v1  = s11 - s1 * s1 * invw;
        float v2  = s22 - s2 * s2 * invw;
        res[k] = cov * rsqrtf(v1 * v2);
        if (k + 1 < KPT) {
            float an = sa[IX(base + WSZ + k)], bn = sb[IX(base + WSZ + k)];
            float ao = sa[IX(base + k)],       bo = sb[IX(base + k)];
            s1  += an - ao;
            s2  += bn - bo;
            s11 += an * an - ao * ao;
            s22 += bn * bn - bo * bo;
            s12 += an * bn - ao * bo;
        }
    }
    __syncthreads();   // done reading sa; reuse as output staging

    #pragma unroll
    for (int k = 0; k < KPT; k++) sa[IX(base + k)] = res[k];
    __syncthreads();

    float* __restrict__ orow = g_corr + (size_t)row * NOUT;
    for (int i = threadIdx.x; i < CHUNK; i += TPB) {
        int j = c0 + i;
        if (j < NOUT) orow[j] = sa[IX(i)];
    }
}

// K2: partial column sums over 64-row groups (coalesced across columns).
__global__ __launch_bounds__(256) void colsum_kernel() {
    int c = blockIdx.x * blockDim.x + threadIdx.x;
    int g = blockIdx.y;
    if (c >= NOUT) return;
    const float* __restrict__ p = g_corr + (size_t)g * ROWS_PER_G * NOUT + c;
    float s = 0.f;
    #pragma unroll
    for (int r = 0; r < ROWS_PER_G; r++) s += p[(size_t)r * NOUT];
    g_partial[g * NOUT + c] = s;
}

// K2b: collapse partials -> avg.
__global__ __launch_bounds__(256) void avg_kernel() {
    int c = blockIdx.x * blockDim.x + threadIdx.x;
    if (c >= NOUT) return;
    float s = 0.f;
    #pragma unroll
    for (int g = 0; g < RGROUPS; g++) s += g_partial[g * NOUT + c];
    g_avg[c] = s * (1.0f / (float)B);
}

// K3: out = relu(corr - avg), vectorized over the linear array.
// TOTAL = B*NOUT is divisible by 4; g_corr and out are contiguous.
#define TOTAL ((size_t)B * NOUT)
__global__ __launch_bounds__(256) void final_kernel(float* __restrict__ out) {
    size_t v4 = (size_t)blockIdx.x * blockDim.x + threadIdx.x;
    size_t i0 = v4 * 4;
    if (i0 >= TOTAL) return;

    float4 cv = *reinterpret_cast<const float4*>(g_corr + i0);
    int c = (int)(i0 % NOUT);

    float a0 = g_avg[c];
    int c1 = c + 1; if (c1 >= NOUT) c1 -= NOUT;
    float a1 = g_avg[c1];
    int c2 = c + 2; if (c2 >= NOUT) c2 -= NOUT;
    float a2 = g_avg[c2];
    int c3 = c + 3; if (c3 >= NOUT) c3 -= NOUT;
    float a3 = g_avg[c3];

    float4 r;
    r.x = cv.x - a0; r.x = r.x > 0.f ? r.x : 0.f;
    r.y = cv.y - a1; r.y = r.y > 0.f ? r.y : 0.f;
    r.z = cv.z - a2; r.z = r.z > 0.f ? r.z : 0.f;
    r.w = cv.w - a3; r.w = r.w > 0.f ? r.w : 0.f;
    *reinterpret_cast<float4*>(out + i0) = r;
}

extern "C" void kernel_launch(void* const* d_in, const int* in_sizes, int n_in,
                              void* d_out, int out_size) {
    const float* x = (const float*)d_in[0];
    float* out = (float*)d_out;

    dim3 g1((NOUT + CHUNK - 1) / CHUNK, B);
    corr_kernel<<<g1, TPB>>>(x);

    dim3 g2((NOUT + 255) / 256, RGROUPS);
    colsum_kernel<<<g2, 256>>>();

    avg_kernel<<<(NOUT + 255) / 256, 256>>>();

    size_t nv4 = TOTAL / 4;
    final_kernel<<<(unsigned)((nv4 + 255) / 256), 256>>>(out);
}